// round 4
// baseline (speedup 1.0000x reference)
#include <cuda_runtime.h>
#include <cstdint>
#include <math.h>

// ---------------- problem constants ----------------
#define T_STEPS 512
#define BATCH   64
#define EMB_D   400
#define HID_D   1152
#define M_ROWS  (T_STEPS * BATCH)   // 32768

// ---------------- scratch (static device memory; no cudaMalloc allowed) ----
__device__ float g_act0[(size_t)M_ROWS * HID_D];        // 151 MB
__device__ float g_act1[(size_t)M_ROWS * HID_D];        // 151 MB
__device__ float g_xw[(size_t)M_ROWS * 4 * HID_D];      // 604 MB
__device__ float g_h[2][BATCH * HID_D];                 // double-buffered hidden state
__device__ unsigned int g_arrive;                       // grid barrier counter

// ---------------- packed f32x2 helpers ----------------
__device__ __forceinline__ unsigned long long pack2(float lo, float hi) {
    unsigned long long r;
    asm("mov.b64 %0, {%1, %2};" : "=l"(r) : "f"(lo), "f"(hi));
    return r;
}
__device__ __forceinline__ void unpack2(unsigned long long v, float& lo, float& hi) {
    asm("mov.b64 {%0, %1}, %2;" : "=f"(lo), "=f"(hi) : "l"(v));
}
__device__ __forceinline__ unsigned long long fma2(unsigned long long a,
                                                   unsigned long long b,
                                                   unsigned long long c) {
    unsigned long long d;
    asm("fma.rn.f32x2 %0, %1, %2, %3;" : "=l"(d) : "l"(a), "l"(b), "l"(c));
    return d;
}

// ---------------- helpers ----------------
__device__ __forceinline__ float sigm(float x) { return 1.0f / (1.0f + expf(-x)); }

__device__ __forceinline__ void grid_barrier(int nctas, unsigned int target) {
    __syncthreads();
    if (threadIdx.x == 0) {
        __threadfence();
        atomicAdd(&g_arrive, 1u);
        unsigned int v;
        do {
            asm volatile("ld.acquire.gpu.u32 %0, [%1];" : "=r"(v) : "l"(&g_arrive) : "memory");
        } while (v < target);
    }
    __syncthreads();
}

__global__ void reset_bar_kernel() { g_arrive = 0u; }

// ---------------- embedding gather ----------------
__global__ void embed_kernel(const int* __restrict__ x, const float* __restrict__ emb,
                             float* __restrict__ out) {
    const int m = blockIdx.x;
    const int tok = x[m];
    const float4* src = (const float4*)(emb + (size_t)tok * EMB_D);
    float4* dst = (float4*)(out + (size_t)m * EMB_D);
    for (int i = threadIdx.x; i < EMB_D / 4; i += blockDim.x) dst[i] = src[i];
}

// ---------------- input projection: out[M][N] = A[M][K] @ W[N][K]^T + (bih+bhh) ----
__global__ void __launch_bounds__(256)
gemm_xw_kernel(const float* __restrict__ A, const float* __restrict__ W,
               const float* __restrict__ bih, const float* __restrict__ bhh,
               float* __restrict__ out, int N, int K) {
    __shared__ float sA[8][128];
    __shared__ float sB[8][128];
    const int tid = threadIdx.x;
    const int tx = tid & 15;
    const int ty = tid >> 4;
    const int m0 = blockIdx.y * 128;
    const int n0 = blockIdx.x * 128;

    const int lrow = tid >> 1;
    const int lkq  = (tid & 1) * 4;
    const float* Ap = A + (size_t)(m0 + lrow) * K + lkq;
    const int nrow = n0 + lrow;
    const float* Wp = W + (size_t)nrow * K + lkq;
    const bool wok = (nrow < N);

    unsigned long long acc2[8][4];
#pragma unroll
    for (int i = 0; i < 8; ++i)
#pragma unroll
        for (int jp = 0; jp < 4; ++jp) acc2[i][jp] = 0ull;

    for (int kt = 0; kt < K; kt += 8) {
        float4 av = *(const float4*)(Ap + kt);
        float4 wv = wok ? *(const float4*)(Wp + kt) : make_float4(0.f, 0.f, 0.f, 0.f);
        sA[lkq + 0][lrow] = av.x; sA[lkq + 1][lrow] = av.y;
        sA[lkq + 2][lrow] = av.z; sA[lkq + 3][lrow] = av.w;
        sB[lkq + 0][lrow] = wv.x; sB[lkq + 1][lrow] = wv.y;
        sB[lkq + 2][lrow] = wv.z; sB[lkq + 3][lrow] = wv.w;
        __syncthreads();
#pragma unroll
        for (int k = 0; k < 8; ++k) {
            float ra[8];
            *(float4*)&ra[0] = *(const float4*)&sA[k][ty * 8];
            *(float4*)&ra[4] = *(const float4*)&sA[k][ty * 8 + 4];
            ulonglong2 rb01 = *(const ulonglong2*)&sB[k][tx * 8];
            ulonglong2 rb23 = *(const ulonglong2*)&sB[k][tx * 8 + 4];
            unsigned long long rb2[4] = {rb01.x, rb01.y, rb23.x, rb23.y};
#pragma unroll
            for (int i = 0; i < 8; ++i) {
                const unsigned long long ai = pack2(ra[i], ra[i]);
#pragma unroll
                for (int jp = 0; jp < 4; ++jp)
                    acc2[i][jp] = fma2(ai, rb2[jp], acc2[i][jp]);
            }
        }
        __syncthreads();
    }

    float bias[8];
#pragma unroll
    for (int j = 0; j < 8; ++j) {
        const int n = n0 + tx * 8 + j;
        bias[j] = (n < N) ? (__ldg(bih + n) + __ldg(bhh + n)) : 0.0f;
    }
#pragma unroll
    for (int i = 0; i < 8; ++i) {
        float vals[8];
#pragma unroll
        for (int jp = 0; jp < 4; ++jp) unpack2(acc2[i][jp], vals[2 * jp], vals[2 * jp + 1]);
        float* orow = out + (size_t)(m0 + ty * 8 + i) * N + n0 + tx * 8;
#pragma unroll
        for (int j = 0; j < 8; ++j)
            if (n0 + tx * 8 + j < N) orow[j] = vals[j] + bias[j];
    }
}

// ---------------- persistent recurrent LSTM layer (v3) ----------------
// Round-3 compute density + round-2 coalesced staging.
// Per CTA: NJ units -> R=4*NJ gate rows, 64 batches. Split-k x2 over halves.
// Thread: 2 rows x 8 batches. Staging: thread loads CONTIGUOUS floats of one
// batch row (full 128B-line coalescing), transposes to k-major SMEM
// (bank-conflict-free: bank = batch mod 32, distinct per lane).
template <int H, int NJ>
__global__ void __launch_bounds__(NJ * 32, 1)
lstm_rec3_kernel(const float* __restrict__ xw, const float* __restrict__ Whh,
                 float* __restrict__ out, int nctas) {
    constexpr int R = 4 * NJ;                  // 32 / 16
    constexpr int THREADS = NJ * 32;           // 256 / 128
    constexpr int HT = THREADS / 2;            // 128 / 64
    constexpr int HALFK = H / 2;               // 576 / 200
    constexpr int NCHUNK = (HALFK + 31) / 32;  // 18 / 7
    constexpr int KPAD = NCHUNK * 32;          // 576 / 224
    constexpr int KG = HT / 64;                // 2 / 1   k-groups per half
    constexpr int KW = 32 / KG;                // 16 / 32 floats staged per thread
    constexpr int F4 = KW / 4;                 // 4 / 8

    extern __shared__ float sm[];
    float* sWT   = sm;                          // [2][KPAD][R]  k-major, zero-padded
    float* sA    = sWT + 2 * KPAD * R;          // [2 half][2 buf][32][64]
    float* sC    = sA + 2 * 2 * 32 * 64;        // [64][R]
    float* sCell = sC + 64 * R;                 // [64*NJ]

    const int tid = threadIdx.x;
    const int j0  = blockIdx.x * NJ;
    const int z   = tid / HT;            // k-half
    const int lt  = tid - z * HT;
    const int rg  = lt >> 3;             // row-pair id
    const int bg  = lt & 7;              // batch group of 8

    // staging mapping: contiguous KW floats of batch row sb, k-group kg
    const int sb = lt & 63;
    const int kg = (KG == 2) ? (lt >> 6) : 0;
    const int kbase = kg * KW;

    // ---- init: W_hh slice transposed (k-major) into SMEM, zero-padded k ----
    for (int idx = tid; idx < 2 * KPAD * R; idx += THREADS) {
        const int zz  = idx / (KPAD * R);
        const int rem = idx - zz * (KPAD * R);
        const int kl  = rem / R;
        const int r   = rem - kl * R;
        float v = 0.0f;
        if (kl < HALFK) {
            const int grow = (r / NJ) * H + j0 + (r % NJ);
            v = Whh[(size_t)grow * H + zz * HALFK + kl];
        }
        sWT[idx] = v;
    }
    for (int i = tid; i < 64 * NJ; i += THREADS) {
        sCell[i] = 0.0f;
        const int b = i / NJ, u = i - b * NJ;
        g_h[0][b * H + j0 + u] = 0.0f;
    }
    unsigned int ep = 1;
    grid_barrier(nctas, ep * (unsigned)nctas); ++ep;

    float* sAz = sA + z * (2 * 32 * 64);
    const float* sWz = sWT + z * (KPAD * R);
    const int g  = (rg * 2) / NJ;
    const int u0 = (rg * 2) % NJ;

    for (int t = 0; t < T_STEPS; ++t) {
        const float* hbuf = g_h[t & 1];
        float* hnext = g_h[1 - (t & 1)];
        const float* hsrc = hbuf + (size_t)sb * H + z * HALFK + kbase;

        // prefetch xw for this thread's outputs (overlaps with mainloop)
        float2 xwv[8];
        if (z == 0) {
            const float* xwbase = xw + (size_t)t * BATCH * (4 * H) + g * H + j0 + u0;
#pragma unroll
            for (int q = 0; q < 8; ++q)
                xwv[q] = __ldg((const float2*)(xwbase + (size_t)(bg * 8 + q) * (4 * H)));
        }

        // prefetch h chunk 0 (contiguous, fully coalesced; OOB-k reads land on
        // valid g_h memory and meet zero weights)
        float4 pf[F4];
#pragma unroll
        for (int j = 0; j < F4; ++j) pf[j] = __ldcg((const float4*)(hsrc + j * 4));

        unsigned long long acc[8];
#pragma unroll
        for (int i = 0; i < 8; ++i) acc[i] = 0ull;

        for (int ci = 0; ci < NCHUNK; ++ci) {
            // stage prefetched chunk (transpose to k-major; bank-conflict-free)
            float* dst = sAz + (ci & 1) * (32 * 64);
#pragma unroll
            for (int j = 0; j < F4; ++j) {
                const int kk = kbase + j * 4;
                dst[(kk + 0) * 64 + sb] = pf[j].x;
                dst[(kk + 1) * 64 + sb] = pf[j].y;
                dst[(kk + 2) * 64 + sb] = pf[j].z;
                dst[(kk + 3) * 64 + sb] = pf[j].w;
            }
            __syncthreads();
            // prefetch next chunk
            if (ci + 1 < NCHUNK) {
                const float* nsrc = hsrc + (ci + 1) * 32;
#pragma unroll
                for (int j = 0; j < F4; ++j) pf[j] = __ldcg((const float4*)(nsrc + j * 4));
            }
            // compute current chunk
            const float* asrc = sAz + (ci & 1) * (32 * 64) + bg * 8;
            const float* wsrc = sWz + ci * 32 * R + rg * 2;
#pragma unroll 8
            for (int kk = 0; kk < 32; ++kk) {
                const ulonglong2 av01 = *(const ulonglong2*)(asrc + kk * 64);
                const ulonglong2 av23 = *(const ulonglong2*)(asrc + kk * 64 + 4);
                const float2 wv = *(const float2*)(wsrc + kk * R);
                const unsigned long long w0 = pack2(wv.x, wv.x);
                const unsigned long long w1 = pack2(wv.y, wv.y);
                acc[0] = fma2(w0, av01.x, acc[0]);
                acc[1] = fma2(w0, av01.y, acc[1]);
                acc[2] = fma2(w0, av23.x, acc[2]);
                acc[3] = fma2(w0, av23.y, acc[3]);
                acc[4] = fma2(w1, av01.x, acc[4]);
                acc[5] = fma2(w1, av01.y, acc[5]);
                acc[6] = fma2(w1, av23.x, acc[6]);
                acc[7] = fma2(w1, av23.y, acc[7]);
            }
        }

        // ---- split-k reduction + xw add through sC ----
        if (z == 1) {
#pragma unroll
            for (int bp = 0; bp < 4; ++bp) {
                float a0lo, a0hi, a1lo, a1hi;
                unpack2(acc[bp], a0lo, a0hi);
                unpack2(acc[4 + bp], a1lo, a1hi);
                const int b0 = bg * 8 + bp * 2;
                *(float2*)(sC + b0 * R + rg * 2) = make_float2(a0lo, a1lo);
                *(float2*)(sC + (b0 + 1) * R + rg * 2) = make_float2(a0hi, a1hi);
            }
        }
        __syncthreads();
        if (z == 0) {
#pragma unroll
            for (int bp = 0; bp < 4; ++bp) {
                float a0lo, a0hi, a1lo, a1hi;
                unpack2(acc[bp], a0lo, a0hi);
                unpack2(acc[4 + bp], a1lo, a1hi);
                const int b0 = bg * 8 + bp * 2;
                float2 p0 = *(const float2*)(sC + b0 * R + rg * 2);
                float2 p1 = *(const float2*)(sC + (b0 + 1) * R + rg * 2);
                p0.x += a0lo + xwv[bp * 2].x;     p0.y += a1lo + xwv[bp * 2].y;
                p1.x += a0hi + xwv[bp * 2 + 1].x; p1.y += a1hi + xwv[bp * 2 + 1].y;
                *(float2*)(sC + b0 * R + rg * 2) = p0;
                *(float2*)(sC + (b0 + 1) * R + rg * 2) = p1;
            }
        }
        __syncthreads();

        // ---- cell/hidden update ----
#pragma unroll
        for (int rep = 0; rep < 2; ++rep) {
            const int i = tid + rep * THREADS;
            if (i < 64 * NJ) {
                const int b = i / NJ, u = i - b * NJ;
                const float gi = sC[b * R + 0 * NJ + u];
                const float gf = sC[b * R + 1 * NJ + u];
                const float gg = sC[b * R + 2 * NJ + u];
                const float go = sC[b * R + 3 * NJ + u];
                float c = sCell[i];
                c = sigm(gf) * c + sigm(gi) * tanhf(gg);
                sCell[i] = c;
                const float hv = sigm(go) * tanhf(c);
                hnext[b * H + j0 + u] = hv;
                out[((size_t)t * BATCH + b) * H + j0 + u] = hv;
            }
        }
        grid_barrier(nctas, ep * (unsigned)nctas); ++ep;
    }
}

// ---------------- launch ----------------
extern "C" void kernel_launch(void* const* d_in, const int* in_sizes, int n_in,
                              void* d_out, int out_size) {
    (void)in_sizes; (void)n_in; (void)out_size;
    const int*   x    = (const int*)d_in[0];
    const float* emb  = (const float*)d_in[1];
    const float* Wih0 = (const float*)d_in[2];
    const float* Whh0 = (const float*)d_in[3];
    const float* bih0 = (const float*)d_in[4];
    const float* bhh0 = (const float*)d_in[5];
    const float* Wih1 = (const float*)d_in[6];
    const float* Whh1 = (const float*)d_in[7];
    const float* bih1 = (const float*)d_in[8];
    const float* bhh1 = (const float*)d_in[9];
    const float* Wih2 = (const float*)d_in[10];
    const float* Whh2 = (const float*)d_in[11];
    const float* bih2 = (const float*)d_in[12];
    const float* bhh2 = (const float*)d_in[13];
    float* out = (float*)d_out;

    float *act0, *act1, *xw;
    cudaGetSymbolAddress((void**)&act0, g_act0);
    cudaGetSymbolAddress((void**)&act1, g_act1);
    cudaGetSymbolAddress((void**)&xw, g_xw);

    const size_t SMEM_BIG = (size_t)(2 * 576 * 32 + 2 * 2 * 32 * 64 + 64 * 32 + 64 * 8) * sizeof(float);
    const size_t SMEM_SMALL = (size_t)(2 * 224 * 16 + 2 * 2 * 32 * 64 + 64 * 16 + 64 * 4) * sizeof(float);
    cudaFuncSetAttribute((const void*)lstm_rec3_kernel<HID_D, 8>,
                         cudaFuncAttributeMaxDynamicSharedMemorySize, (int)SMEM_BIG);
    cudaFuncSetAttribute((const void*)lstm_rec3_kernel<EMB_D, 4>,
                         cudaFuncAttributeMaxDynamicSharedMemorySize, (int)SMEM_SMALL);

    // embedding
    embed_kernel<<<M_ROWS, 128>>>(x, emb, act0);

    // layer 0: din=400, H=1152
    gemm_xw_kernel<<<dim3(36, 256), 256>>>(act0, Wih0, bih0, bhh0, xw, 4 * HID_D, EMB_D);
    reset_bar_kernel<<<1, 1>>>();
    lstm_rec3_kernel<HID_D, 8><<<144, 256, SMEM_BIG>>>(xw, Whh0, act1, 144);

    // layer 1: din=1152, H=1152
    gemm_xw_kernel<<<dim3(36, 256), 256>>>(act1, Wih1, bih1, bhh1, xw, 4 * HID_D, HID_D);
    reset_bar_kernel<<<1, 1>>>();
    lstm_rec3_kernel<HID_D, 8><<<144, 256, SMEM_BIG>>>(xw, Whh1, act0, 144);

    // layer 2: din=1152, H=400
    gemm_xw_kernel<<<dim3(13, 256), 256>>>(act0, Wih2, bih2, bhh2, xw, 4 * EMB_D, HID_D);
    reset_bar_kernel<<<1, 1>>>();
    lstm_rec3_kernel<EMB_D, 4><<<100, 128, SMEM_SMALL>>>(xw, Whh2, out, 100);
}

// round 6
// speedup vs baseline: 2.3980x; 2.3980x over previous
#include <cuda_runtime.h>
#include <cstdint>
#include <math.h>

// ---------------- problem constants ----------------
#define T_STEPS 512
#define BATCH   64
#define EMB_D   400
#define HID_D   1152
#define M_ROWS  (T_STEPS * BATCH)   // 32768

// ---------------- scratch (static device memory; no cudaMalloc allowed) ----
__device__ float g_act0[(size_t)M_ROWS * HID_D];        // 151 MB
__device__ float g_act1[(size_t)M_ROWS * HID_D];        // 151 MB
__device__ float g_xw[(size_t)M_ROWS * 4 * HID_D];      // 604 MB
__device__ float g_h[2][BATCH * HID_D];                 // k-major hidden: [H][64], 2 bufs
__device__ unsigned int g_arrive;                       // grid barrier counter

// ---------------- packed f32x2 helpers ----------------
__device__ __forceinline__ unsigned long long pack2(float lo, float hi) {
    unsigned long long r;
    asm("mov.b64 %0, {%1, %2};" : "=l"(r) : "f"(lo), "f"(hi));
    return r;
}
__device__ __forceinline__ void unpack2(unsigned long long v, float& lo, float& hi) {
    asm("mov.b64 {%0, %1}, %2;" : "=f"(lo), "=f"(hi) : "l"(v));
}
__device__ __forceinline__ unsigned long long fma2(unsigned long long a,
                                                   unsigned long long b,
                                                   unsigned long long c) {
    unsigned long long d;
    asm("fma.rn.f32x2 %0, %1, %2, %3;" : "=l"(d) : "l"(a), "l"(b), "l"(c));
    return d;
}

__device__ __forceinline__ void cpasync16(uint32_t saddr, const float* g) {
    asm volatile("cp.async.cg.shared.global [%0], [%1], 16;" :: "r"(saddr), "l"(g));
}
__device__ __forceinline__ void cpcommit() {
    asm volatile("cp.async.commit_group;" ::: "memory");
}

// ---------------- helpers ----------------
__device__ __forceinline__ float sigm(float x) { return 1.0f / (1.0f + expf(-x)); }

__device__ __forceinline__ void grid_barrier(int nctas, unsigned int target) {
    __syncthreads();
    if (threadIdx.x == 0) {
        __threadfence();
        atomicAdd(&g_arrive, 1u);
        unsigned int v;
        do {
            asm volatile("ld.acquire.gpu.u32 %0, [%1];" : "=r"(v) : "l"(&g_arrive) : "memory");
        } while (v < target);
    }
    __syncthreads();
}

__global__ void reset_bar_kernel() { g_arrive = 0u; }

// ---------------- embedding gather ----------------
__global__ void embed_kernel(const int* __restrict__ x, const float* __restrict__ emb,
                             float* __restrict__ out) {
    const int m = blockIdx.x;
    const int tok = x[m];
    const float4* src = (const float4*)(emb + (size_t)tok * EMB_D);
    float4* dst = (float4*)(out + (size_t)m * EMB_D);
    for (int i = threadIdx.x; i < EMB_D / 4; i += blockDim.x) dst[i] = src[i];
}

// ---------------- input projection: out[M][N] = A[M][K] @ W[N][K]^T + (bih+bhh) ----
__global__ void __launch_bounds__(256)
gemm_xw_kernel(const float* __restrict__ A, const float* __restrict__ W,
               const float* __restrict__ bih, const float* __restrict__ bhh,
               float* __restrict__ out, int N, int K) {
    __shared__ float sA[8][128];
    __shared__ float sB[8][128];
    const int tid = threadIdx.x;
    const int tx = tid & 15;
    const int ty = tid >> 4;
    const int m0 = blockIdx.y * 128;
    const int n0 = blockIdx.x * 128;

    const int lrow = tid >> 1;
    const int lkq  = (tid & 1) * 4;
    const float* Ap = A + (size_t)(m0 + lrow) * K + lkq;
    const int nrow = n0 + lrow;
    const float* Wp = W + (size_t)nrow * K + lkq;
    const bool wok = (nrow < N);

    unsigned long long acc2[8][4];
#pragma unroll
    for (int i = 0; i < 8; ++i)
#pragma unroll
        for (int jp = 0; jp < 4; ++jp) acc2[i][jp] = 0ull;

    for (int kt = 0; kt < K; kt += 8) {
        float4 av = *(const float4*)(Ap + kt);
        float4 wv = wok ? *(const float4*)(Wp + kt) : make_float4(0.f, 0.f, 0.f, 0.f);
        sA[lkq + 0][lrow] = av.x; sA[lkq + 1][lrow] = av.y;
        sA[lkq + 2][lrow] = av.z; sA[lkq + 3][lrow] = av.w;
        sB[lkq + 0][lrow] = wv.x; sB[lkq + 1][lrow] = wv.y;
        sB[lkq + 2][lrow] = wv.z; sB[lkq + 3][lrow] = wv.w;
        __syncthreads();
#pragma unroll
        for (int k = 0; k < 8; ++k) {
            float ra[8];
            *(float4*)&ra[0] = *(const float4*)&sA[k][ty * 8];
            *(float4*)&ra[4] = *(const float4*)&sA[k][ty * 8 + 4];
            ulonglong2 rb01 = *(const ulonglong2*)&sB[k][tx * 8];
            ulonglong2 rb23 = *(const ulonglong2*)&sB[k][tx * 8 + 4];
            unsigned long long rb2[4] = {rb01.x, rb01.y, rb23.x, rb23.y};
#pragma unroll
            for (int i = 0; i < 8; ++i) {
                const unsigned long long ai = pack2(ra[i], ra[i]);
#pragma unroll
                for (int jp = 0; jp < 4; ++jp)
                    acc2[i][jp] = fma2(ai, rb2[jp], acc2[i][jp]);
            }
        }
        __syncthreads();
    }

    float bias[8];
#pragma unroll
    for (int j = 0; j < 8; ++j) {
        const int n = n0 + tx * 8 + j;
        bias[j] = (n < N) ? (__ldg(bih + n) + __ldg(bhh + n)) : 0.0f;
    }
#pragma unroll
    for (int i = 0; i < 8; ++i) {
        float vals[8];
#pragma unroll
        for (int jp = 0; jp < 4; ++jp) unpack2(acc2[i][jp], vals[2 * jp], vals[2 * jp + 1]);
        float* orow = out + (size_t)(m0 + ty * 8 + i) * N + n0 + tx * 8;
#pragma unroll
        for (int j = 0; j < 8; ++j)
            if (n0 + tx * 8 + j < N) orow[j] = vals[j] + bias[j];
    }
}

// ---------------- persistent recurrent LSTM layer (v4) ----------------
// CTA: 8 hidden units (32 gate rows) x 64 batches. Grid = H/8 (144 / 50).
// 8 warps = 8 k-slices of KS = H/8 each (split-k across warps).
// Thread (lane): rgrp = lane&3 -> rows rgrp*8..+7; bg = lane>>2 -> batches bg*8..+7.
// Per kk: 2 LDS.128 (h) + 2 LDS.128 (w row-pairs, packed free) + 8 h-packs + 32 FFMA2
//   => 1.0 B LDS/MAC. FMA-bound by design.
// g_h is K-MAJOR [H][64]: staging chunks are contiguous -> cp.async, no transpose.
template <int H>
__global__ void __launch_bounds__(256, 1)
lstm_rec4_kernel(const float* __restrict__ xw, const float* __restrict__ Whh,
                 float* __restrict__ out, int nctas) {
    constexpr int KS    = H / 8;                 // k per slice: 144 / 50
    constexpr int NCH   = (KS + 15) / 16;        // chunks: 9 / 4
    constexpr int KPADZ = NCH * 16;              // padded k per slice: 144 / 64
    constexpr int WFL   = 8 * KPADZ * 32;        // W floats in SMEM

    extern __shared__ float sm[];
    float* sW     = sm;                          // [8 z][KPADZ][32 rows]
    float* sStage = sW + WFL;                    // [2 buf][8 z][16 k][64 b] = 16384 fl
    float* sC     = sStage;                      // alias: [8 z][64 b][32 r] partials
    float* sCell  = sStage + 16384;              // [512]

    const int tid  = threadIdx.x;
    const int z    = tid >> 5;                   // warp = k-slice
    const int lane = tid & 31;
    const int rgrp = lane & 3;                   // rows rgrp*8..+7
    const int bg   = lane >> 2;                  // batches bg*8..+7
    const int j0   = blockIdx.x * 8;             // unit offset

    // ---- init: W_hh slice -> SMEM [z][kp][32], zero-padded k ----
    for (int idx = tid; idx < WFL; idx += 256) {
        const int r  = idx & 31;
        const int kl = idx >> 5;                 // z*KPADZ + kp
        const int zz = kl / KPADZ;
        const int kp = kl - zz * KPADZ;
        float v = 0.0f;
        if (kp < KS) {
            const int grow = (r >> 3) * H + j0 + (r & 7);
            v = Whh[(size_t)grow * H + zz * KS + kp];
        }
        sW[idx] = v;
    }
    // zero cell + this CTA's rows of h buffer 0 (k-major)
    for (int i = tid; i < 512; i += 256) {
        sCell[i] = 0.0f;
        const int u = i & 7, b = i >> 3;
        g_h[0][(j0 + u) * 64 + b] = 0.0f;
    }
    unsigned int ep = 1;
    grid_barrier(nctas, ep * (unsigned)nctas); ++ep;

    // reduction cells: c0 = tid, c1 = tid + 256; cell = b*8 + u
    const int c0b = tid >> 3, c0u = tid & 7;
    const int c1b = (tid + 256) >> 3, c1u = tid & 7;

    const uint32_t stage_s = (uint32_t)__cvta_generic_to_shared(sStage);
    const float* wbase = sW + z * KPADZ * 32;

    for (int t = 0; t < T_STEPS; ++t) {
        const float* hbuf = g_h[t & 1];
        float* hnext = g_h[1 - (t & 1)];

        // prefetch xw for this thread's 2 cells x 4 gates
        float xwv[2][4];
        {
            const float* xb0 = xw + ((size_t)t * 64 + c0b) * (4 * H) + j0 + c0u;
            const float* xb1 = xw + ((size_t)t * 64 + c1b) * (4 * H) + j0 + c1u;
#pragma unroll
            for (int g = 0; g < 4; ++g) {
                xwv[0][g] = __ldg(xb0 + g * H);
                xwv[1][g] = __ldg(xb1 + g * H);
            }
        }

        // issue chunk 0 staging: thread stages float4 #tid of slice j, for j=0..7
#pragma unroll
        for (int j = 0; j < 8; ++j)
            cpasync16(stage_s + (uint32_t)(j * 256 + tid) * 16,
                      hbuf + (j * KS) * 64 + tid * 4);
        cpcommit();

        unsigned long long acc[4][8];            // [row-pair][batch]
#pragma unroll
        for (int rp = 0; rp < 4; ++rp)
#pragma unroll
            for (int b = 0; b < 8; ++b) acc[rp][b] = 0ull;

        for (int ci = 0; ci < NCH; ++ci) {
            if (ci + 1 < NCH) {
                const int buf = (ci + 1) & 1;
#pragma unroll
                for (int j = 0; j < 8; ++j)
                    cpasync16(stage_s + (uint32_t)(buf * 2048 + j * 256 + tid) * 16,
                              hbuf + (j * KS + (ci + 1) * 16) * 64 + tid * 4);
                cpcommit();
                asm volatile("cp.async.wait_group 1;" ::: "memory");
            } else {
                asm volatile("cp.async.wait_group 0;" ::: "memory");
            }
            __syncthreads();

            const float4* a4 = (const float4*)sStage + (ci & 1) * 2048 + z * 256;
            const ulonglong2* w2 = (const ulonglong2*)(wbase + ci * 16 * 32) + rgrp * 2;
#pragma unroll
            for (int kk = 0; kk < 16; ++kk) {
                const float4 h01 = a4[kk * 16 + bg * 2];
                const float4 h23 = a4[kk * 16 + bg * 2 + 1];
                const ulonglong2 wA = w2[kk * 8];
                const ulonglong2 wB = w2[kk * 8 + 1];
                const unsigned long long hp0 = pack2(h01.x, h01.x);
                const unsigned long long hp1 = pack2(h01.y, h01.y);
                const unsigned long long hp2 = pack2(h01.z, h01.z);
                const unsigned long long hp3 = pack2(h01.w, h01.w);
                const unsigned long long hp4 = pack2(h23.x, h23.x);
                const unsigned long long hp5 = pack2(h23.y, h23.y);
                const unsigned long long hp6 = pack2(h23.z, h23.z);
                const unsigned long long hp7 = pack2(h23.w, h23.w);
                acc[0][0] = fma2(wA.x, hp0, acc[0][0]);
                acc[1][0] = fma2(wA.y, hp0, acc[1][0]);
                acc[2][0] = fma2(wB.x, hp0, acc[2][0]);
                acc[3][0] = fma2(wB.y, hp0, acc[3][0]);
                acc[0][1] = fma2(wA.x, hp1, acc[0][1]);
                acc[1][1] = fma2(wA.y, hp1, acc[1][1]);
                acc[2][1] = fma2(wB.x, hp1, acc[2][1]);
                acc[3][1] = fma2(wB.y, hp1, acc[3][1]);
                acc[0][2] = fma2(wA.x, hp2, acc[0][2]);
                acc[1][2] = fma2(wA.y, hp2, acc[1][2]);
                acc[2][2] = fma2(wB.x, hp2, acc[2][2]);
                acc[3][2] = fma2(wB.y, hp2, acc[3][2]);
                acc[0][3] = fma2(wA.x, hp3, acc[0][3]);
                acc[1][3] = fma2(wA.y, hp3, acc[1][3]);
                acc[2][3] = fma2(wB.x, hp3, acc[2][3]);
                acc[3][3] = fma2(wB.y, hp3, acc[3][3]);
                acc[0][4] = fma2(wA.x, hp4, acc[0][4]);
                acc[1][4] = fma2(wA.y, hp4, acc[1][4]);
                acc[2][4] = fma2(wB.x, hp4, acc[2][4]);
                acc[3][4] = fma2(wB.y, hp4, acc[3][4]);
                acc[0][5] = fma2(wA.x, hp5, acc[0][5]);
                acc[1][5] = fma2(wA.y, hp5, acc[1][5]);
                acc[2][5] = fma2(wB.x, hp5, acc[2][5]);
                acc[3][5] = fma2(wB.y, hp5, acc[3][5]);
                acc[0][6] = fma2(wA.x, hp6, acc[0][6]);
                acc[1][6] = fma2(wA.y, hp6, acc[1][6]);
                acc[2][6] = fma2(wB.x, hp6, acc[2][6]);
                acc[3][6] = fma2(wB.y, hp6, acc[3][6]);
                acc[0][7] = fma2(wA.x, hp7, acc[0][7]);
                acc[1][7] = fma2(wA.y, hp7, acc[1][7]);
                acc[2][7] = fma2(wB.x, hp7, acc[2][7]);
                acc[3][7] = fma2(wB.y, hp7, acc[3][7]);
            }
        }
        __syncthreads();   // protect stage buffers before partial-store alias

        // ---- store split-k partials: sC[z][b][32 r] ----
#pragma unroll
        for (int b = 0; b < 8; ++b) {
            float* p = sC + z * 2048 + (bg * 8 + b) * 32 + rgrp * 8;
            *(ulonglong2*)p       = make_ulonglong2(acc[0][b], acc[1][b]);
            *(ulonglong2*)(p + 4) = make_ulonglong2(acc[2][b], acc[3][b]);
        }
        __syncthreads();

        // ---- reduce 8 partials, add xw, gate math, write h (k-major) + out ----
#pragma unroll
        for (int cc = 0; cc < 2; ++cc) {
            const int b = cc ? c1b : c0b;
            const int u = cc ? c1u : c0u;
            float gsum[4];
#pragma unroll
            for (int g = 0; g < 4; ++g) {
                const int o = b * 32 + g * 8 + u;
                float s = sC[o] + sC[2048 + o];
                s += sC[2 * 2048 + o] + sC[3 * 2048 + o];
                s += sC[4 * 2048 + o] + sC[5 * 2048 + o];
                s += sC[6 * 2048 + o] + sC[7 * 2048 + o];
                gsum[g] = s + xwv[cc][g];
            }
            const int cell = b * 8 + u;
            float c = sCell[cell];
            c = sigm(gsum[1]) * c + sigm(gsum[0]) * tanhf(gsum[2]);
            sCell[cell] = c;
            const float hv = sigm(gsum[3]) * tanhf(c);
            hnext[(j0 + u) * 64 + b] = hv;
            out[((size_t)t * 64 + b) * H + j0 + u] = hv;
        }
        grid_barrier(nctas, ep * (unsigned)nctas); ++ep;
    }
}

// ---------------- launch ----------------
extern "C" void kernel_launch(void* const* d_in, const int* in_sizes, int n_in,
                              void* d_out, int out_size) {
    (void)in_sizes; (void)n_in; (void)out_size;
    const int*   x    = (const int*)d_in[0];
    const float* emb  = (const float*)d_in[1];
    const float* Wih0 = (const float*)d_in[2];
    const float* Whh0 = (const float*)d_in[3];
    const float* bih0 = (const float*)d_in[4];
    const float* bhh0 = (const float*)d_in[5];
    const float* Wih1 = (const float*)d_in[6];
    const float* Whh1 = (const float*)d_in[7];
    const float* bih1 = (const float*)d_in[8];
    const float* bhh1 = (const float*)d_in[9];
    const float* Wih2 = (const float*)d_in[10];
    const float* Whh2 = (const float*)d_in[11];
    const float* bih2 = (const float*)d_in[12];
    const float* bhh2 = (const float*)d_in[13];
    float* out = (float*)d_out;

    float *act0, *act1, *xw;
    cudaGetSymbolAddress((void**)&act0, g_act0);
    cudaGetSymbolAddress((void**)&act1, g_act1);
    cudaGetSymbolAddress((void**)&xw, g_xw);

    // SMEM: W + stage(16384) + cell(512) floats
    const size_t SMEM_BIG   = (size_t)(8 * 144 * 32 + 16384 + 512) * sizeof(float); // 215040 B
    const size_t SMEM_SMALL = (size_t)(8 * 64 * 32 + 16384 + 512) * sizeof(float);  // 133120 B
    cudaFuncSetAttribute((const void*)lstm_rec4_kernel<HID_D>,
                         cudaFuncAttributeMaxDynamicSharedMemorySize, (int)SMEM_BIG);
    cudaFuncSetAttribute((const void*)lstm_rec4_kernel<EMB_D>,
                         cudaFuncAttributeMaxDynamicSharedMemorySize, (int)SMEM_SMALL);

    // embedding
    embed_kernel<<<M_ROWS, 128>>>(x, emb, act0);

    // layer 0: din=400, H=1152
    gemm_xw_kernel<<<dim3(36, 256), 256>>>(act0, Wih0, bih0, bhh0, xw, 4 * HID_D, EMB_D);
    reset_bar_kernel<<<1, 1>>>();
    lstm_rec4_kernel<HID_D><<<144, 256, SMEM_BIG>>>(xw, Whh0, act1, 144);

    // layer 1: din=1152, H=1152
    gemm_xw_kernel<<<dim3(36, 256), 256>>>(act1, Wih1, bih1, bhh1, xw, 4 * HID_D, HID_D);
    reset_bar_kernel<<<1, 1>>>();
    lstm_rec4_kernel<HID_D><<<144, 256, SMEM_BIG>>>(xw, Whh1, act0, 144);

    // layer 2: din=1152, H=400
    gemm_xw_kernel<<<dim3(13, 256), 256>>>(act0, Wih2, bih2, bhh2, xw, 4 * EMB_D, HID_D);
    reset_bar_kernel<<<1, 1>>>();
    lstm_rec4_kernel<EMB_D><<<50, 256, SMEM_SMALL>>>(xw, Whh2, out, 50);
}

// round 7
// speedup vs baseline: 2.4405x; 1.0177x over previous
#include <cuda_runtime.h>
#include <cstdint>
#include <math.h>

// ---------------- problem constants ----------------
#define T_STEPS 512
#define BATCH   64
#define EMB_D   400
#define HID_D   1152
#define M_ROWS  (T_STEPS * BATCH)   // 32768

// ---------------- scratch (static device memory; no cudaMalloc allowed) ----
__device__ float g_act0[(size_t)M_ROWS * HID_D];        // 151 MB
__device__ float g_act1[(size_t)M_ROWS * HID_D];        // 151 MB
__device__ float g_xw[(size_t)M_ROWS * 4 * HID_D];      // 604 MB
__device__ float g_h[2][BATCH * HID_D];                 // k-major hidden: [H][64], 2 bufs
__device__ unsigned int g_arrive;                       // grid barrier counter

// ---------------- packed f32x2 helpers ----------------
__device__ __forceinline__ unsigned long long pack2(float lo, float hi) {
    unsigned long long r;
    asm("mov.b64 %0, {%1, %2};" : "=l"(r) : "f"(lo), "f"(hi));
    return r;
}
__device__ __forceinline__ void unpack2(unsigned long long v, float& lo, float& hi) {
    asm("mov.b64 {%0, %1}, %2;" : "=f"(lo), "=f"(hi) : "l"(v));
}
__device__ __forceinline__ unsigned long long fma2(unsigned long long a,
                                                   unsigned long long b,
                                                   unsigned long long c) {
    unsigned long long d;
    asm("fma.rn.f32x2 %0, %1, %2, %3;" : "=l"(d) : "l"(a), "l"(b), "l"(c));
    return d;
}

__device__ __forceinline__ void cpasync16(uint32_t saddr, const float* g) {
    asm volatile("cp.async.cg.shared.global [%0], [%1], 16;" :: "r"(saddr), "l"(g));
}
__device__ __forceinline__ void cpcommit() {
    asm volatile("cp.async.commit_group;" ::: "memory");
}

// ---------------- helpers ----------------
__device__ __forceinline__ float sigm(float x) { return 1.0f / (1.0f + expf(-x)); }

__device__ __forceinline__ void grid_barrier(int nctas, unsigned int target) {
    __syncthreads();
    if (threadIdx.x == 0) {
        __threadfence();
        atomicAdd(&g_arrive, 1u);
        unsigned int v;
        do {
            asm volatile("ld.acquire.gpu.u32 %0, [%1];" : "=r"(v) : "l"(&g_arrive) : "memory");
        } while (v < target);
    }
    __syncthreads();
}

__global__ void reset_bar_kernel() { g_arrive = 0u; }

// ---------------- embedding gather ----------------
__global__ void embed_kernel(const int* __restrict__ x, const float* __restrict__ emb,
                             float* __restrict__ out) {
    const int m = blockIdx.x;
    const int tok = x[m];
    const float4* src = (const float4*)(emb + (size_t)tok * EMB_D);
    float4* dst = (float4*)(out + (size_t)m * EMB_D);
    for (int i = threadIdx.x; i < EMB_D / 4; i += blockDim.x) dst[i] = src[i];
}

// ---------------- input projection v2: out[M][N] = A[M][K] @ W[N][K]^T + bias ----
// 256x128 block tile, BK=16, 256 threads, 16m x 8n per-thread micro-tile.
// Ping-pong SMEM buffers + register-prefetched global loads, 1 sync per tile.
// sA swizzled (float idx m -> m ^ ((m>>1)&0x1C)) for conflict-free 64B-stride LDS.
__global__ void __launch_bounds__(256, 1)
gemm_xw2_kernel(const float* __restrict__ A, const float* __restrict__ W,
                const float* __restrict__ bih, const float* __restrict__ bhh,
                float* __restrict__ out, int N, int K) {
    extern __shared__ float smg[];
    float* sAs = smg;                    // [2][16][256]
    float* sBs = smg + 2 * 16 * 256;     // [2][16][128]

    const int tid = threadIdx.x;
    const int tm  = tid & 15;            // 16 m rows: tm*16..tm*16+15
    const int tn  = tid >> 4;            // 8 n cols: tn*8..tn*8+7
    const int m0  = blockIdx.y * 256;
    const int n0  = blockIdx.x * 128;

    // staging: A row m0+tid (16 contiguous k), B row n0+(tid>>1) (8 k each)
    const float* Ap = A + (size_t)(m0 + tid) * K;
    const int fst  = tid ^ ((tid >> 1) & 0x1C);   // swizzled A store column
    const int bn   = tid >> 1;
    const int bkq  = (tid & 1) * 8;
    const float* Wp = W + (size_t)(n0 + bn) * K + bkq;
    const bool bok  = (n0 + bn) < N;

    // compute-side swizzled A offsets (4 x 16B units)
    int aoff[4];
#pragma unroll
    for (int j = 0; j < 4; ++j) {
        const int m = tm * 16 + j * 4;
        aoff[j] = m ^ ((m >> 1) & 0x1C);
    }

    const int NT = K / 16;

    unsigned long long acc[16][4];
#pragma unroll
    for (int i = 0; i < 16; ++i)
#pragma unroll
        for (int jp = 0; jp < 4; ++jp) acc[i][jp] = 0ull;

    const float4 z4 = make_float4(0.f, 0.f, 0.f, 0.f);
    float4 apf[4], bpf[2];

    // prologue: load + store tile 0
#pragma unroll
    for (int j = 0; j < 4; ++j) apf[j] = *(const float4*)(Ap + j * 4);
    bpf[0] = bok ? *(const float4*)(Wp)     : z4;
    bpf[1] = bok ? *(const float4*)(Wp + 4) : z4;
    {
        float* sa = sAs;                 // buf 0
        float* sb = sBs;
#pragma unroll
        for (int j = 0; j < 4; ++j) {
            sa[(j * 4 + 0) * 256 + fst] = apf[j].x;
            sa[(j * 4 + 1) * 256 + fst] = apf[j].y;
            sa[(j * 4 + 2) * 256 + fst] = apf[j].z;
            sa[(j * 4 + 3) * 256 + fst] = apf[j].w;
        }
        sb[(bkq + 0) * 128 + bn] = bpf[0].x;
        sb[(bkq + 1) * 128 + bn] = bpf[0].y;
        sb[(bkq + 2) * 128 + bn] = bpf[0].z;
        sb[(bkq + 3) * 128 + bn] = bpf[0].w;
        sb[(bkq + 4) * 128 + bn] = bpf[1].x;
        sb[(bkq + 5) * 128 + bn] = bpf[1].y;
        sb[(bkq + 6) * 128 + bn] = bpf[1].z;
        sb[(bkq + 7) * 128 + bn] = bpf[1].w;
    }
    __syncthreads();

    for (int it = 0; it < NT; ++it) {
        const int nxt = it + 1;
        if (nxt < NT) {   // prefetch next tile to registers (overlaps compute)
            const float* ap2 = Ap + nxt * 16;
#pragma unroll
            for (int j = 0; j < 4; ++j) apf[j] = *(const float4*)(ap2 + j * 4);
            const float* wp2 = Wp + nxt * 16;
            bpf[0] = bok ? *(const float4*)(wp2)     : z4;
            bpf[1] = bok ? *(const float4*)(wp2 + 4) : z4;
        }
        // compute current buffer
        {
            const float* sa = sAs + (it & 1) * (16 * 256);
            const float* sb = sBs + (it & 1) * (16 * 128);
#pragma unroll
            for (int k = 0; k < 16; ++k) {
                float ra[16];
                *(float4*)&ra[0]  = *(const float4*)(sa + k * 256 + aoff[0]);
                *(float4*)&ra[4]  = *(const float4*)(sa + k * 256 + aoff[1]);
                *(float4*)&ra[8]  = *(const float4*)(sa + k * 256 + aoff[2]);
                *(float4*)&ra[12] = *(const float4*)(sa + k * 256 + aoff[3]);
                const ulonglong2 b01 = *(const ulonglong2*)(sb + k * 128 + tn * 8);
                const ulonglong2 b23 = *(const ulonglong2*)(sb + k * 128 + tn * 8 + 4);
                unsigned long long rb[4] = {b01.x, b01.y, b23.x, b23.y};
#pragma unroll
                for (int i = 0; i < 16; ++i) {
                    const unsigned long long ai = pack2(ra[i], ra[i]);
#pragma unroll
                    for (int jp = 0; jp < 4; ++jp)
                        acc[i][jp] = fma2(ai, rb[jp], acc[i][jp]);
                }
            }
        }
        // stage next tile into the other buffer
        if (nxt < NT) {
            float* sa = sAs + (nxt & 1) * (16 * 256);
            float* sb = sBs + (nxt & 1) * (16 * 128);
#pragma unroll
            for (int j = 0; j < 4; ++j) {
                sa[(j * 4 + 0) * 256 + fst] = apf[j].x;
                sa[(j * 4 + 1) * 256 + fst] = apf[j].y;
                sa[(j * 4 + 2) * 256 + fst] = apf[j].z;
                sa[(j * 4 + 3) * 256 + fst] = apf[j].w;
            }
            sb[(bkq + 0) * 128 + bn] = bpf[0].x;
            sb[(bkq + 1) * 128 + bn] = bpf[0].y;
            sb[(bkq + 2) * 128 + bn] = bpf[0].z;
            sb[(bkq + 3) * 128 + bn] = bpf[0].w;
            sb[(bkq + 4) * 128 + bn] = bpf[1].x;
            sb[(bkq + 5) * 128 + bn] = bpf[1].y;
            sb[(bkq + 6) * 128 + bn] = bpf[1].z;
            sb[(bkq + 7) * 128 + bn] = bpf[1].w;
        }
        __syncthreads();
    }

    // epilogue
    float bias[8];
#pragma unroll
    for (int jj = 0; jj < 8; ++jj) {
        const int n = n0 + tn * 8 + jj;
        bias[jj] = (n < N) ? (__ldg(bih + n) + __ldg(bhh + n)) : 0.0f;
    }
    const bool full = (n0 + 128 <= N);
#pragma unroll
    for (int i = 0; i < 16; ++i) {
        float vals[8];
#pragma unroll
        for (int jp = 0; jp < 4; ++jp) unpack2(acc[i][jp], vals[2 * jp], vals[2 * jp + 1]);
#pragma unroll
        for (int jj = 0; jj < 8; ++jj) vals[jj] += bias[jj];
        float* orow = out + (size_t)(m0 + tm * 16 + i) * N + n0 + tn * 8;
        if (full) {
            *(float4*)orow       = make_float4(vals[0], vals[1], vals[2], vals[3]);
            *(float4*)(orow + 4) = make_float4(vals[4], vals[5], vals[6], vals[7]);
        } else {
#pragma unroll
            for (int jj = 0; jj < 8; ++jj)
                if (n0 + tn * 8 + jj < N) orow[jj] = vals[jj];
        }
    }
}

// ---------------- persistent recurrent LSTM layer (v4, unchanged) ----------------
template <int H>
__global__ void __launch_bounds__(256, 1)
lstm_rec4_kernel(const float* __restrict__ xw, const float* __restrict__ Whh,
                 float* __restrict__ out, int nctas) {
    constexpr int KS    = H / 8;                 // k per slice: 144 / 50
    constexpr int NCH   = (KS + 15) / 16;        // chunks: 9 / 4
    constexpr int KPADZ = NCH * 16;              // padded k per slice
    constexpr int WFL   = 8 * KPADZ * 32;        // W floats in SMEM

    extern __shared__ float sm[];
    float* sW     = sm;                          // [8 z][KPADZ][32 rows]
    float* sStage = sW + WFL;                    // [2 buf][8 z][16 k][64 b]
    float* sC     = sStage;                      // alias: [8 z][64 b][32 r]
    float* sCell  = sStage + 16384;              // [512]

    const int tid  = threadIdx.x;
    const int z    = tid >> 5;
    const int lane = tid & 31;
    const int rgrp = lane & 3;
    const int bg   = lane >> 2;
    const int j0   = blockIdx.x * 8;

    for (int idx = tid; idx < WFL; idx += 256) {
        const int r  = idx & 31;
        const int kl = idx >> 5;
        const int zz = kl / KPADZ;
        const int kp = kl - zz * KPADZ;
        float v = 0.0f;
        if (kp < KS) {
            const int grow = (r >> 3) * H + j0 + (r & 7);
            v = Whh[(size_t)grow * H + zz * KS + kp];
        }
        sW[idx] = v;
    }
    for (int i = tid; i < 512; i += 256) {
        sCell[i] = 0.0f;
        const int u = i & 7, b = i >> 3;
        g_h[0][(j0 + u) * 64 + b] = 0.0f;
    }
    unsigned int ep = 1;
    grid_barrier(nctas, ep * (unsigned)nctas); ++ep;

    const int c0b = tid >> 3, c0u = tid & 7;
    const int c1b = (tid + 256) >> 3, c1u = tid & 7;

    const uint32_t stage_s = (uint32_t)__cvta_generic_to_shared(sStage);
    const float* wbase = sW + z * KPADZ * 32;

    for (int t = 0; t < T_STEPS; ++t) {
        const float* hbuf = g_h[t & 1];
        float* hnext = g_h[1 - (t & 1)];

        float xwv[2][4];
        {
            const float* xb0 = xw + ((size_t)t * 64 + c0b) * (4 * H) + j0 + c0u;
            const float* xb1 = xw + ((size_t)t * 64 + c1b) * (4 * H) + j0 + c1u;
#pragma unroll
            for (int g = 0; g < 4; ++g) {
                xwv[0][g] = __ldg(xb0 + g * H);
                xwv[1][g] = __ldg(xb1 + g * H);
            }
        }

#pragma unroll
        for (int j = 0; j < 8; ++j)
            cpasync16(stage_s + (uint32_t)(j * 256 + tid) * 16,
                      hbuf + (j * KS) * 64 + tid * 4);
        cpcommit();

        unsigned long long acc[4][8];
#pragma unroll
        for (int rp = 0; rp < 4; ++rp)
#pragma unroll
            for (int b = 0; b < 8; ++b) acc[rp][b] = 0ull;

        for (int ci = 0; ci < NCH; ++ci) {
            if (ci + 1 < NCH) {
                const int buf = (ci + 1) & 1;
#pragma unroll
                for (int j = 0; j < 8; ++j)
                    cpasync16(stage_s + (uint32_t)(buf * 2048 + j * 256 + tid) * 16,
                              hbuf + (j * KS + (ci + 1) * 16) * 64 + tid * 4);
                cpcommit();
                asm volatile("cp.async.wait_group 1;" ::: "memory");
            } else {
                asm volatile("cp.async.wait_group 0;" ::: "memory");
            }
            __syncthreads();

            const float4* a4 = (const float4*)sStage + (ci & 1) * 2048 + z * 256;
            const ulonglong2* w2 = (const ulonglong2*)(wbase + ci * 16 * 32) + rgrp * 2;
#pragma unroll
            for (int kk = 0; kk < 16; ++kk) {
                const float4 h01 = a4[kk * 16 + bg * 2];
                const float4 h23 = a4[kk * 16 + bg * 2 + 1];
                const ulonglong2 wA = w2[kk * 8];
                const ulonglong2 wB = w2[kk * 8 + 1];
                const unsigned long long hp0 = pack2(h01.x, h01.x);
                const unsigned long long hp1 = pack2(h01.y, h01.y);
                const unsigned long long hp2 = pack2(h01.z, h01.z);
                const unsigned long long hp3 = pack2(h01.w, h01.w);
                const unsigned long long hp4 = pack2(h23.x, h23.x);
                const unsigned long long hp5 = pack2(h23.y, h23.y);
                const unsigned long long hp6 = pack2(h23.z, h23.z);
                const unsigned long long hp7 = pack2(h23.w, h23.w);
                acc[0][0] = fma2(wA.x, hp0, acc[0][0]);
                acc[1][0] = fma2(wA.y, hp0, acc[1][0]);
                acc[2][0] = fma2(wB.x, hp0, acc[2][0]);
                acc[3][0] = fma2(wB.y, hp0, acc[3][0]);
                acc[0][1] = fma2(wA.x, hp1, acc[0][1]);
                acc[1][1] = fma2(wA.y, hp1, acc[1][1]);
                acc[2][1] = fma2(wB.x, hp1, acc[2][1]);
                acc[3][1] = fma2(wB.y, hp1, acc[3][1]);
                acc[0][2] = fma2(wA.x, hp2, acc[0][2]);
                acc[1][2] = fma2(wA.y, hp2, acc[1][2]);
                acc[2][2] = fma2(wB.x, hp2, acc[2][2]);
                acc[3][2] = fma2(wB.y, hp2, acc[3][2]);
                acc[0][3] = fma2(wA.x, hp3, acc[0][3]);
                acc[1][3] = fma2(wA.y, hp3, acc[1][3]);
                acc[2][3] = fma2(wB.x, hp3, acc[2][3]);
                acc[3][3] = fma2(wB.y, hp3, acc[3][3]);
                acc[0][4] = fma2(wA.x, hp4, acc[0][4]);
                acc[1][4] = fma2(wA.y, hp4, acc[1][4]);
                acc[2][4] = fma2(wB.x, hp4, acc[2][4]);
                acc[3][4] = fma2(wB.y, hp4, acc[3][4]);
                acc[0][5] = fma2(wA.x, hp5, acc[0][5]);
                acc[1][5] = fma2(wA.y, hp5, acc[1][5]);
                acc[2][5] = fma2(wB.x, hp5, acc[2][5]);
                acc[3][5] = fma2(wB.y, hp5, acc[3][5]);
                acc[0][6] = fma2(wA.x, hp6, acc[0][6]);
                acc[1][6] = fma2(wA.y, hp6, acc[1][6]);
                acc[2][6] = fma2(wB.x, hp6, acc[2][6]);
                acc[3][6] = fma2(wB.y, hp6, acc[3][6]);
                acc[0][7] = fma2(wA.x, hp7, acc[0][7]);
                acc[1][7] = fma2(wA.y, hp7, acc[1][7]);
                acc[2][7] = fma2(wB.x, hp7, acc[2][7]);
                acc[3][7] = fma2(wB.y, hp7, acc[3][7]);
            }
        }
        __syncthreads();

#pragma unroll
        for (int b = 0; b < 8; ++b) {
            float* p = sC + z * 2048 + (bg * 8 + b) * 32 + rgrp * 8;
            *(ulonglong2*)p       = make_ulonglong2(acc[0][b], acc[1][b]);
            *(ulonglong2*)(p + 4) = make_ulonglong2(acc[2][b], acc[3][b]);
        }
        __syncthreads();

#pragma unroll
        for (int cc = 0; cc < 2; ++cc) {
            const int b = cc ? c1b : c0b;
            const int u = cc ? c1u : c0u;
            float gsum[4];
#pragma unroll
            for (int g = 0; g < 4; ++g) {
                const int o = b * 32 + g * 8 + u;
                float s = sC[o] + sC[2048 + o];
                s += sC[2 * 2048 + o] + sC[3 * 2048 + o];
                s += sC[4 * 2048 + o] + sC[5 * 2048 + o];
                s += sC[6 * 2048 + o] + sC[7 * 2048 + o];
                gsum[g] = s + xwv[cc][g];
            }
            const int cell = b * 8 + u;
            float c = sCell[cell];
            c = sigm(gsum[1]) * c + sigm(gsum[0]) * tanhf(gsum[2]);
            sCell[cell] = c;
            const float hv = sigm(gsum[3]) * tanhf(c);
            hnext[(j0 + u) * 64 + b] = hv;
            out[((size_t)t * 64 + b) * H + j0 + u] = hv;
        }
        grid_barrier(nctas, ep * (unsigned)nctas); ++ep;
    }
}

// ---------------- launch ----------------
extern "C" void kernel_launch(void* const* d_in, const int* in_sizes, int n_in,
                              void* d_out, int out_size) {
    (void)in_sizes; (void)n_in; (void)out_size;
    const int*   x    = (const int*)d_in[0];
    const float* emb  = (const float*)d_in[1];
    const float* Wih0 = (const float*)d_in[2];
    const float* Whh0 = (const float*)d_in[3];
    const float* bih0 = (const float*)d_in[4];
    const float* bhh0 = (const float*)d_in[5];
    const float* Wih1 = (const float*)d_in[6];
    const float* Whh1 = (const float*)d_in[7];
    const float* bih1 = (const float*)d_in[8];
    const float* bhh1 = (const float*)d_in[9];
    const float* Wih2 = (const float*)d_in[10];
    const float* Whh2 = (const float*)d_in[11];
    const float* bih2 = (const float*)d_in[12];
    const float* bhh2 = (const float*)d_in[13];
    float* out = (float*)d_out;

    float *act0, *act1, *xw;
    cudaGetSymbolAddress((void**)&act0, g_act0);
    cudaGetSymbolAddress((void**)&act1, g_act1);
    cudaGetSymbolAddress((void**)&xw, g_xw);

    const size_t SMEM_GEMM  = (size_t)(2 * 16 * 256 + 2 * 16 * 128) * sizeof(float); // 49152
    const size_t SMEM_BIG   = (size_t)(8 * 144 * 32 + 16384 + 512) * sizeof(float);  // 215040
    const size_t SMEM_SMALL = (size_t)(8 * 64 * 32 + 16384 + 512) * sizeof(float);   // 133120
    cudaFuncSetAttribute((const void*)gemm_xw2_kernel,
                         cudaFuncAttributeMaxDynamicSharedMemorySize, (int)SMEM_GEMM);
    cudaFuncSetAttribute((const void*)lstm_rec4_kernel<HID_D>,
                         cudaFuncAttributeMaxDynamicSharedMemorySize, (int)SMEM_BIG);
    cudaFuncSetAttribute((const void*)lstm_rec4_kernel<EMB_D>,
                         cudaFuncAttributeMaxDynamicSharedMemorySize, (int)SMEM_SMALL);

    // embedding
    embed_kernel<<<M_ROWS, 128>>>(x, emb, act0);

    // layer 0: din=400, H=1152
    gemm_xw2_kernel<<<dim3(36, 128), 256, SMEM_GEMM>>>(act0, Wih0, bih0, bhh0, xw, 4 * HID_D, EMB_D);
    reset_bar_kernel<<<1, 1>>>();
    lstm_rec4_kernel<HID_D><<<144, 256, SMEM_BIG>>>(xw, Whh0, act1, 144);

    // layer 1: din=1152, H=1152
    gemm_xw2_kernel<<<dim3(36, 128), 256, SMEM_GEMM>>>(act1, Wih1, bih1, bhh1, xw, 4 * HID_D, HID_D);
    reset_bar_kernel<<<1, 1>>>();
    lstm_rec4_kernel<HID_D><<<144, 256, SMEM_BIG>>>(xw, Whh1, act0, 144);

    // layer 2: din=1152, H=400
    gemm_xw2_kernel<<<dim3(13, 128), 256, SMEM_GEMM>>>(act0, Wih2, bih2, bhh2, xw, 4 * EMB_D, HID_D);
    reset_bar_kernel<<<1, 1>>>();
    lstm_rec4_kernel<EMB_D><<<50, 256, SMEM_SMALL>>>(xw, Whh2, out, 50);
}